// round 1
// baseline (speedup 1.0000x reference)
#include <cuda_runtime.h>
#include <math.h>

#define NUM_BINS    128
#define NUM_NETS    100000
#define NUM_NODES   200000
#define NUM_MOVABLE 180000
#define NUM_PINS    400000

// Exact binary-representable constants
#define SB       7.8125f            // bin size (1000/128), exact in fp32
#define INV_SB   0.128f             // 1/SB (approx; corrected by bin_of fixup)
#define BIN_AREA 61.03515625f       // SB*SB, exact
#define CXU (1.0f / (BIN_AREA * 1.5f))
#define CYU (1.0f / (BIN_AREA * 1.4f))

// Scratch: 2D difference array (x-major), x = cx-scaled map, y = cy-scaled map
__device__ float2 g_diff[NUM_BINS * NUM_BINS];
__device__ float  g_util[NUM_BINS * NUM_BINS];

__device__ __forceinline__ int bin_of(float v) {
    int b = (int)(v * INV_SB);
    b = max(0, min(NUM_BINS - 1, b));
    // fixup for INV_SB rounding near bin boundaries
    if (v < (float)b * SB) b--;
    else if (v >= (float)(b + 1) * SB) b++;
    return max(0, min(NUM_BINS - 1, b));
}

__device__ __forceinline__ void red_add2(float2* addr, float a, float b) {
    asm volatile("red.global.add.v2.f32 [%0], {%1, %2};"
                 :: "l"(addr), "f"(a), "f"(b) : "memory");
}

__global__ void zero_kernel() {
    int i = blockIdx.x * blockDim.x + threadIdx.x;
    if (i < NUM_BINS * NUM_BINS) g_diff[i] = make_float2(0.f, 0.f);
}

// Per net: bbox over its pins, then 16 corner updates of the 2D difference
// array (outer product of the two 4-entry 1D difference vectors).
__global__ void net_kernel(const float* __restrict__ pin_pos,
                           const float* __restrict__ net_weights,
                           const int*   __restrict__ netpin_start,
                           const int*   __restrict__ flat_netpin) {
    int n = blockIdx.x * blockDim.x + threadIdx.x;
    if (n >= NUM_NETS) return;
    int s = netpin_start[n];
    int e = netpin_start[n + 1];
    if (e <= s) return;

    float xmn = 3.4e38f, xmx = -3.4e38f, ymn = 3.4e38f, ymx = -3.4e38f;
    for (int i = s; i < e; i++) {
        int p = flat_netpin[i];
        float px = __ldg(pin_pos + p);
        float py = __ldg(pin_pos + p + NUM_PINS);
        xmn = fminf(xmn, px); xmx = fmaxf(xmx, px);
        ymn = fminf(ymn, py); ymx = fmaxf(ymx, py);
    }

    float w  = net_weights[n];
    float dx = xmx - xmn, dy = ymx - ymn;
    float cx = (dy > 0.f) ? (w / dy) : 0.f;   // scales map_x
    float cy = (dx > 0.f) ? (w / dx) : 0.f;   // scales map_y
    if (cx == 0.f && cy == 0.f) return;

    int x0 = bin_of(xmn), x1 = bin_of(xmx);
    int y0 = bin_of(ymn), y1 = bin_of(ymx);

    float v0x = (float)(x0 + 1) * SB - xmn;   // overlap of bin x0 (ignoring xmax)
    float v1x = xmx - (float)x1 * SB;         // overlap of bin x1 (ignoring xmin)
    float v0y = (float)(y0 + 1) * SB - ymn;
    float v1y = ymx - (float)y1 * SB;

    // 1D difference of the overlap profile: <=4 nonzeros each axis.
    int   xp[4] = { x0, x0 + 1, x1, x1 + 1 };
    float xv[4] = { v0x, SB - v0x, v1x - SB, -v1x };
    int   yp[4] = { y0, y0 + 1, y1, y1 + 1 };
    float yv[4] = { v0y, SB - v0y, v1y - SB, -v1y };

    #pragma unroll
    for (int i = 0; i < 4; i++) {
        if (xp[i] >= NUM_BINS) continue;
        int row = xp[i] * NUM_BINS;
        #pragma unroll
        for (int j = 0; j < 4; j++) {
            if (yp[j] >= NUM_BINS) continue;
            float v = xv[i] * yv[j];
            red_add2(&g_diff[row + yp[j]], v * cx, v * cy);
        }
    }
}

// Single block: 2D inclusive prefix sum of g_diff (rows then columns),
// then compute util = clip(max(map_x/capx, map_y/capy), 0.5, 2.0).
__global__ void prefix_util_kernel() {
    int t = threadIdx.x;   // 0..127
    // Phase 1: prefix along y within row t
    {
        float ax = 0.f, ay = 0.f;
        #pragma unroll 4
        for (int y = 0; y < NUM_BINS; y++) {
            float2 d = g_diff[t * NUM_BINS + y];
            ax += d.x; ay += d.y;
            g_diff[t * NUM_BINS + y] = make_float2(ax, ay);
        }
    }
    __syncthreads();
    // Phase 2: prefix along x within column t, emit util
    {
        float ax = 0.f, ay = 0.f;
        #pragma unroll 4
        for (int x = 0; x < NUM_BINS; x++) {
            float2 d = g_diff[x * NUM_BINS + t];
            ax += d.x; ay += d.y;
            float u = fmaxf(ax * CXU, ay * CYU);
            u = fminf(fmaxf(u, 0.5f), 2.0f);
            g_util[x * NUM_BINS + t] = u;
        }
    }
}

// Per movable node: sum overlap(x)*overlap(y)*util over the <=3x3 covered bins.
__global__ void node_kernel(const float* __restrict__ pos,
                            const float* __restrict__ nszx,
                            const float* __restrict__ nszy,
                            float* __restrict__ out) {
    int m = blockIdx.x * blockDim.x + threadIdx.x;
    if (m >= NUM_MOVABLE) return;
    float nx = pos[m], ny = pos[m + NUM_NODES];
    float sx = nszx[m], sy = nszy[m];
    float xh = nx + sx, yh = ny + sy;

    int x0 = bin_of(nx), x1 = bin_of(xh);
    int y0 = bin_of(ny), y1 = bin_of(yh);

    float acc = 0.f;
    for (int x = x0; x <= x1; x++) {
        float ox = fminf((float)(x + 1) * SB, xh) - fmaxf((float)x * SB, nx);
        ox = fmaxf(ox, 0.f);
        float a2 = 0.f;
        for (int y = y0; y <= y1; y++) {
            float oy = fminf((float)(y + 1) * SB, yh) - fmaxf((float)y * SB, ny);
            oy = fmaxf(oy, 0.f);
            a2 += oy * __ldg(&g_util[x * NUM_BINS + y]);
        }
        acc += ox * a2;
    }
    out[m] = acc;
}

extern "C" void kernel_launch(void* const* d_in, const int* in_sizes, int n_in,
                              void* d_out, int out_size) {
    const float* pos          = (const float*)d_in[0];
    const float* pin_pos      = (const float*)d_in[1];
    const float* node_size_x  = (const float*)d_in[2];
    const float* node_size_y  = (const float*)d_in[3];
    const float* net_weights  = (const float*)d_in[4];
    const int*   netpin_start = (const int*)d_in[5];
    const int*   flat_netpin  = (const int*)d_in[6];
    float* out = (float*)d_out;

    zero_kernel<<<(NUM_BINS * NUM_BINS + 255) / 256, 256>>>();
    net_kernel<<<(NUM_NETS + 255) / 256, 256>>>(pin_pos, net_weights,
                                                netpin_start, flat_netpin);
    prefix_util_kernel<<<1, NUM_BINS>>>();
    node_kernel<<<(NUM_MOVABLE + 255) / 256, 256>>>(pos, node_size_x,
                                                    node_size_y, out);
}

// round 2
// speedup vs baseline: 2.6044x; 2.6044x over previous
#include <cuda_runtime.h>
#include <math.h>

#define NUM_BINS    128
#define NUM_NETS    100000
#define NUM_NODES   200000
#define NUM_MOVABLE 180000
#define NUM_PINS    400000

// Exact binary-representable constants
#define SB       7.8125f            // bin size (1000/128), exact in fp32
#define INV_SB   0.128f             // 1/SB (approx; corrected by bin_of fixup)
#define BIN_AREA 61.03515625f       // SB*SB, exact
#define CXU (1.0f / (BIN_AREA * 1.5f))
#define CYU (1.0f / (BIN_AREA * 1.4f))

// Scratch. g_diff is zero at module load; scan_rows_kernel re-zeroes it each
// invocation, so every kernel_launch call sees zeros (graph-replay safe).
__device__ float2 g_diff[NUM_BINS * NUM_BINS];   // 2D difference array, [x*128+y]
__device__ float2 g_pref[NUM_BINS * NUM_BINS];   // after y-prefix
__device__ float  g_util[NUM_BINS * NUM_BINS];   // final utilization, [x*128+y]

__device__ __forceinline__ int bin_of(float v) {
    int b = (int)(v * INV_SB);
    b = max(0, min(NUM_BINS - 1, b));
    if (v < (float)b * SB) b--;
    else if (v >= (float)(b + 1) * SB) b++;
    return max(0, min(NUM_BINS - 1, b));
}

__device__ __forceinline__ void red_add2(float2* addr, float a, float b) {
    asm volatile("red.global.add.v2.f32 [%0], {%1, %2};"
                 :: "l"(addr), "f"(a), "f"(b) : "memory");
}

// Emit the 4 y-deltas for one x-row of the 2D difference outer product.
__device__ __forceinline__ void emit_row(float2* rowp, float a, float b,
                                         int y0, int y1,
                                         float yv0, float yv1, float yv2, float yv3) {
    red_add2(rowp + y0, a * yv0, b * yv0);
    if (y0 + 1 < NUM_BINS) red_add2(rowp + y0 + 1, a * yv1, b * yv1);
    red_add2(rowp + y1, a * yv2, b * yv2);
    if (y1 + 1 < NUM_BINS) red_add2(rowp + y1 + 1, a * yv3, b * yv3);
}

// Per net: bbox over pins, then 16 corner updates of the 2D difference array.
// Fast path: exactly 4 pins, aligned (true for this dataset) -> int4 index
// load + 8 independent pin gathers issued as one batch.
__global__ void net_kernel(const float* __restrict__ pin_pos,
                           const float* __restrict__ net_weights,
                           const int*   __restrict__ netpin_start,
                           const int*   __restrict__ flat_netpin) {
    int n = blockIdx.x * blockDim.x + threadIdx.x;
    if (n >= NUM_NETS) return;
    int s = __ldg(netpin_start + n);
    int e = __ldg(netpin_start + n + 1);

    float xmn, xmx, ymn, ymx;
    if (e - s == 4 && (s & 3) == 0) {
        int4 p = __ldg((const int4*)(flat_netpin + s));
        float px0 = __ldg(pin_pos + p.x);
        float px1 = __ldg(pin_pos + p.y);
        float px2 = __ldg(pin_pos + p.z);
        float px3 = __ldg(pin_pos + p.w);
        float py0 = __ldg(pin_pos + p.x + NUM_PINS);
        float py1 = __ldg(pin_pos + p.y + NUM_PINS);
        float py2 = __ldg(pin_pos + p.z + NUM_PINS);
        float py3 = __ldg(pin_pos + p.w + NUM_PINS);
        xmn = fminf(fminf(px0, px1), fminf(px2, px3));
        xmx = fmaxf(fmaxf(px0, px1), fmaxf(px2, px3));
        ymn = fminf(fminf(py0, py1), fminf(py2, py3));
        ymx = fmaxf(fmaxf(py0, py1), fmaxf(py2, py3));
    } else {
        if (e <= s) return;
        xmn = 3.4e38f; xmx = -3.4e38f; ymn = 3.4e38f; ymx = -3.4e38f;
        for (int i = s; i < e; i++) {
            int p = __ldg(flat_netpin + i);
            float px = __ldg(pin_pos + p);
            float py = __ldg(pin_pos + p + NUM_PINS);
            xmn = fminf(xmn, px); xmx = fmaxf(xmx, px);
            ymn = fminf(ymn, py); ymx = fmaxf(ymx, py);
        }
    }

    float w  = __ldg(net_weights + n);
    float dx = xmx - xmn, dy = ymx - ymn;
    float cx = (dy > 0.f) ? (w / dy) : 0.f;   // scales map_x
    float cy = (dx > 0.f) ? (w / dx) : 0.f;   // scales map_y
    if (cx == 0.f && cy == 0.f) return;

    int x0 = bin_of(xmn), x1 = bin_of(xmx);
    int y0 = bin_of(ymn), y1 = bin_of(ymx);

    float v0x = (float)(x0 + 1) * SB - xmn;
    float v1x = xmx - (float)x1 * SB;
    float v0y = (float)(y0 + 1) * SB - ymn;
    float v1y = ymx - (float)y1 * SB;

    float yv0 = v0y, yv1 = SB - v0y, yv2 = v1y - SB, yv3 = -v1y;

    // x-side difference entries: (x0, v0x), (x0+1, SB-v0x), (x1, v1x-SB), (x1+1, -v1x)
    emit_row(g_diff + x0 * NUM_BINS, v0x * cx, v0x * cy, y0, y1, yv0, yv1, yv2, yv3);
    if (x0 + 1 < NUM_BINS) {
        float xv = SB - v0x;
        emit_row(g_diff + (x0 + 1) * NUM_BINS, xv * cx, xv * cy, y0, y1, yv0, yv1, yv2, yv3);
    }
    {
        float xv = v1x - SB;
        emit_row(g_diff + x1 * NUM_BINS, xv * cx, xv * cy, y0, y1, yv0, yv1, yv2, yv3);
    }
    if (x1 + 1 < NUM_BINS) {
        float xv = -v1x;
        emit_row(g_diff + (x1 + 1) * NUM_BINS, xv * cx, xv * cy, y0, y1, yv0, yv1, yv2, yv3);
    }
}

__device__ __forceinline__ float2 block_scan_128(float2 v, float2* wsum) {
    int t = threadIdx.x, lane = t & 31, w = t >> 5;
    #pragma unroll
    for (int o = 1; o < 32; o <<= 1) {
        float ax = __shfl_up_sync(0xffffffffu, v.x, o);
        float ay = __shfl_up_sync(0xffffffffu, v.y, o);
        if (lane >= o) { v.x += ax; v.y += ay; }
    }
    if (lane == 31) wsum[w] = v;
    __syncthreads();
    float ox = 0.f, oy = 0.f;
    #pragma unroll
    for (int k = 0; k < 3; k++)
        if (w > k) { ox += wsum[k].x; oy += wsum[k].y; }
    v.x += ox; v.y += oy;
    return v;
}

// One block per x-row: inclusive prefix along y; also re-zero g_diff.
__global__ void scan_rows_kernel() {
    __shared__ float2 wsum[4];
    int x = blockIdx.x, t = threadIdx.x;
    float2 v = g_diff[x * NUM_BINS + t];
    v = block_scan_128(v, wsum);
    g_pref[x * NUM_BINS + t] = v;
    g_diff[x * NUM_BINS + t] = make_float2(0.f, 0.f);
}

// One block per y-column: inclusive prefix along x; emit util.
__global__ void scan_cols_util_kernel() {
    __shared__ float2 wsum[4];
    int y = blockIdx.x, t = threadIdx.x;
    float2 v = g_pref[t * NUM_BINS + y];
    v = block_scan_128(v, wsum);
    float u = fmaxf(v.x * CXU, v.y * CYU);
    u = fminf(fmaxf(u, 0.5f), 2.0f);
    g_util[t * NUM_BINS + y] = u;
}

// Per movable node: sum overlap(x)*overlap(y)*util over the covered bins.
__global__ void node_kernel(const float* __restrict__ pos,
                            const float* __restrict__ nszx,
                            const float* __restrict__ nszy,
                            float* __restrict__ out) {
    int m = blockIdx.x * blockDim.x + threadIdx.x;
    if (m >= NUM_MOVABLE) return;
    float nx = __ldg(pos + m), ny = __ldg(pos + m + NUM_NODES);
    float sx = __ldg(nszx + m), sy = __ldg(nszy + m);
    float xh = nx + sx, yh = ny + sy;

    int x0 = bin_of(nx), x1 = bin_of(xh);
    int y0 = bin_of(ny), y1 = bin_of(yh);

    float acc = 0.f;
    for (int x = x0; x <= x1; x++) {
        float ox = fminf((float)(x + 1) * SB, xh) - fmaxf((float)x * SB, nx);
        ox = fmaxf(ox, 0.f);
        float a2 = 0.f;
        for (int y = y0; y <= y1; y++) {
            float oy = fminf((float)(y + 1) * SB, yh) - fmaxf((float)y * SB, ny);
            oy = fmaxf(oy, 0.f);
            a2 += oy * __ldg(&g_util[x * NUM_BINS + y]);
        }
        acc += ox * a2;
    }
    out[m] = acc;
}

extern "C" void kernel_launch(void* const* d_in, const int* in_sizes, int n_in,
                              void* d_out, int out_size) {
    const float* pos          = (const float*)d_in[0];
    const float* pin_pos      = (const float*)d_in[1];
    const float* node_size_x  = (const float*)d_in[2];
    const float* node_size_y  = (const float*)d_in[3];
    const float* net_weights  = (const float*)d_in[4];
    const int*   netpin_start = (const int*)d_in[5];
    const int*   flat_netpin  = (const int*)d_in[6];
    float* out = (float*)d_out;

    net_kernel<<<(NUM_NETS + 127) / 128, 128>>>(pin_pos, net_weights,
                                                netpin_start, flat_netpin);
    scan_rows_kernel<<<NUM_BINS, NUM_BINS>>>();
    scan_cols_util_kernel<<<NUM_BINS, NUM_BINS>>>();
    node_kernel<<<(NUM_MOVABLE + 127) / 128, 128>>>(pos, node_size_x,
                                                    node_size_y, out);
}

// round 3
// speedup vs baseline: 2.8710x; 1.1023x over previous
#include <cuda_runtime.h>
#include <math.h>

#define NUM_BINS    128
#define NUM_NETS    100000
#define NUM_NODES   200000
#define NUM_MOVABLE 180000
#define NUM_PINS    400000

#define SB       7.8125f            // bin size (1000/128), exact in fp32
#define INV_SB   0.128f             // approx 1/SB; corrected in bin_of
#define BIN_AREA 61.03515625f       // SB*SB, exact
#define CXU (1.0f / (BIN_AREA * 1.5f))
#define CYU (1.0f / (BIN_AREA * 1.4f))

// Scratch. g_diff zero at load; scan kernel re-zeroes each invocation.
__device__ __align__(16) float2 g_diff[NUM_BINS * NUM_BINS]; // diff array [x*128+y]
__device__ float2 g_pref[NUM_BINS * NUM_BINS];               // after y-prefix
__device__ float  g_util[NUM_BINS * NUM_BINS];               // final util [x*128+y]
__device__ int    g_ctr;                                     // scan grid barrier (reset by node_kernel)

__device__ __forceinline__ int bin_of(float v) {
    int b = (int)(v * INV_SB);
    b = max(0, min(NUM_BINS - 1, b));
    if (v < (float)b * SB) b--;
    else if (v >= (float)(b + 1) * SB) b++;
    return max(0, min(NUM_BINS - 1, b));
}

__device__ __forceinline__ void red_add2(float2* addr, float a, float b) {
    asm volatile("red.global.add.v2.f32 [%0], {%1, %2};"
                 :: "l"(addr), "f"(a), "f"(b) : "memory");
}
__device__ __forceinline__ void red_add4(float2* addr, float a0, float b0,
                                         float a1, float b1) {
    asm volatile("red.global.add.v4.f32 [%0], {%1, %2, %3, %4};"
                 :: "l"(addr), "f"(a0), "f"(b0), "f"(a1), "f"(b1) : "memory");
}

// Emit the <=4 y-deltas of one x-row; merge adjacent pairs into v4 when the
// first index is even (16B-aligned).
__device__ __forceinline__ void emit_row(float2* rowp, float a, float b,
                                         int y0, int y1,
                                         float yv0, float yv1, float yv2, float yv3) {
    if ((y0 & 1) == 0) {            // y0 even => y0+1 <= 127, aligned pair
        red_add4(rowp + y0, a * yv0, b * yv0, a * yv1, b * yv1);
    } else {
        red_add2(rowp + y0, a * yv0, b * yv0);
        if (y0 + 1 < NUM_BINS) red_add2(rowp + y0 + 1, a * yv1, b * yv1);
    }
    if ((y1 & 1) == 0) {
        red_add4(rowp + y1, a * yv2, b * yv2, a * yv3, b * yv3);
    } else {
        red_add2(rowp + y1, a * yv2, b * yv2);
        if (y1 + 1 < NUM_BINS) red_add2(rowp + y1 + 1, a * yv3, b * yv3);
    }
}

__global__ void net_kernel(const float* __restrict__ pin_pos,
                           const float* __restrict__ net_weights,
                           const int*   __restrict__ netpin_start,
                           const int*   __restrict__ flat_netpin) {
    int n = blockIdx.x * blockDim.x + threadIdx.x;
    if (n >= NUM_NETS) return;
    int s = __ldg(netpin_start + n);
    int e = __ldg(netpin_start + n + 1);

    float xmn, xmx, ymn, ymx;
    if (e - s == 4 && (s & 3) == 0) {       // hot path for this dataset
        int4 p = __ldg((const int4*)(flat_netpin + s));
        float px0 = __ldg(pin_pos + p.x);
        float px1 = __ldg(pin_pos + p.y);
        float px2 = __ldg(pin_pos + p.z);
        float px3 = __ldg(pin_pos + p.w);
        float py0 = __ldg(pin_pos + p.x + NUM_PINS);
        float py1 = __ldg(pin_pos + p.y + NUM_PINS);
        float py2 = __ldg(pin_pos + p.z + NUM_PINS);
        float py3 = __ldg(pin_pos + p.w + NUM_PINS);
        xmn = fminf(fminf(px0, px1), fminf(px2, px3));
        xmx = fmaxf(fmaxf(px0, px1), fmaxf(px2, px3));
        ymn = fminf(fminf(py0, py1), fminf(py2, py3));
        ymx = fmaxf(fmaxf(py0, py1), fmaxf(py2, py3));
    } else {
        if (e <= s) return;
        xmn = 3.4e38f; xmx = -3.4e38f; ymn = 3.4e38f; ymx = -3.4e38f;
        for (int i = s; i < e; i++) {
            int p = __ldg(flat_netpin + i);
            float px = __ldg(pin_pos + p);
            float py = __ldg(pin_pos + p + NUM_PINS);
            xmn = fminf(xmn, px); xmx = fmaxf(xmx, px);
            ymn = fminf(ymn, py); ymx = fmaxf(ymx, py);
        }
    }

    float w  = __ldg(net_weights + n);
    float dx = xmx - xmn, dy = ymx - ymn;
    float cx = (dy > 0.f) ? (w / dy) : 0.f;
    float cy = (dx > 0.f) ? (w / dx) : 0.f;
    if (cx == 0.f && cy == 0.f) return;

    int x0 = bin_of(xmn), x1 = bin_of(xmx);
    int y0 = bin_of(ymn), y1 = bin_of(ymx);

    float v0x = (float)(x0 + 1) * SB - xmn;
    float v1x = xmx - (float)x1 * SB;
    float v0y = (float)(y0 + 1) * SB - ymn;
    float v1y = ymx - (float)y1 * SB;

    float yv0 = v0y, yv1 = SB - v0y, yv2 = v1y - SB, yv3 = -v1y;

    emit_row(g_diff + x0 * NUM_BINS, v0x * cx, v0x * cy, y0, y1, yv0, yv1, yv2, yv3);
    if (x0 + 1 < NUM_BINS) {
        float xv = SB - v0x;
        emit_row(g_diff + (x0 + 1) * NUM_BINS, xv * cx, xv * cy, y0, y1, yv0, yv1, yv2, yv3);
    }
    {
        float xv = v1x - SB;
        emit_row(g_diff + x1 * NUM_BINS, xv * cx, xv * cy, y0, y1, yv0, yv1, yv2, yv3);
    }
    if (x1 + 1 < NUM_BINS) {
        float xv = -v1x;
        emit_row(g_diff + (x1 + 1) * NUM_BINS, xv * cx, xv * cy, y0, y1, yv0, yv1, yv2, yv3);
    }
}

__device__ __forceinline__ float2 block_scan_128(float2 v, float2* wsum) {
    int t = threadIdx.x, lane = t & 31, w = t >> 5;
    #pragma unroll
    for (int o = 1; o < 32; o <<= 1) {
        float ax = __shfl_up_sync(0xffffffffu, v.x, o);
        float ay = __shfl_up_sync(0xffffffffu, v.y, o);
        if (lane >= o) { v.x += ax; v.y += ay; }
    }
    if (lane == 31) wsum[w] = v;
    __syncthreads();
    float ox = 0.f, oy = 0.f;
    #pragma unroll
    for (int k = 0; k < 3; k++)
        if (w > k) { ox += wsum[k].x; oy += wsum[k].y; }
    v.x += ox; v.y += oy;
    return v;
}

// 128 blocks (all wave-1 resident on 148 SMs): block b scans row b (y-prefix,
// re-zeroing g_diff), grid-barriers via monotone counter, then scans column b
// (x-prefix) and emits util. g_ctr is reset by node_kernel afterwards.
__global__ void scan_fused_kernel() {
    __shared__ float2 wsum[4];
    int b = blockIdx.x, t = threadIdx.x;

    // Phase 1: y-prefix of row b
    float2 v = g_diff[b * NUM_BINS + t];
    v = block_scan_128(v, wsum);
    g_pref[b * NUM_BINS + t] = v;
    g_diff[b * NUM_BINS + t] = make_float2(0.f, 0.f);

    // Grid barrier (arrive-only; counter never decremented here)
    __threadfence();
    __syncthreads();
    if (t == 0) {
        atomicAdd(&g_ctr, 1);
        while (atomicAdd(&g_ctr, 0) < NUM_BINS) __nanosleep(40);
    }
    __syncthreads();
    __threadfence();

    // Phase 2: x-prefix of column b, emit util
    float2 c;
    {
        const float2* p = g_pref + t * NUM_BINS + b;
        asm volatile("ld.global.cg.v2.f32 {%0, %1}, [%2];"
                     : "=f"(c.x), "=f"(c.y) : "l"(p));
    }
    __syncthreads();   // reuse wsum safely
    c = block_scan_128(c, wsum);
    float u = fmaxf(c.x * CXU, c.y * CYU);
    u = fminf(fmaxf(u, 0.5f), 2.0f);
    g_util[t * NUM_BINS + b] = u;
}

// Per movable node: branch-free 3x3 (span <= 3 bins/axis since size < 8 < 2*SB).
// Overlap formula yields 0 for bins beyond the span; indices clamped for safety.
__global__ void node_kernel(const float* __restrict__ pos,
                            const float* __restrict__ nszx,
                            const float* __restrict__ nszy,
                            float* __restrict__ out) {
    int m = blockIdx.x * blockDim.x + threadIdx.x;
    if (m >= NUM_MOVABLE) return;
    if (m == 0) g_ctr = 0;                    // reset scan barrier for next replay
    float nx = __ldg(pos + m), ny = __ldg(pos + m + NUM_NODES);
    float sx = __ldg(nszx + m), sy = __ldg(nszy + m);
    float xh = nx + sx, yh = ny + sy;

    int x0 = bin_of(nx);
    int y0 = bin_of(ny);

    float oxv[3], oyv[3];
    int   xi[3], yi[3];
    #pragma unroll
    for (int k = 0; k < 3; k++) {
        float bx = (float)(x0 + k) * SB;
        oxv[k] = fmaxf(fminf(bx + SB, xh) - fmaxf(bx, nx), 0.f);
        xi[k]  = min(x0 + k, NUM_BINS - 1) * NUM_BINS;
        float by = (float)(y0 + k) * SB;
        oyv[k] = fmaxf(fminf(by + SB, yh) - fmaxf(by, ny), 0.f);
        yi[k]  = min(y0 + k, NUM_BINS - 1);
    }

    float u[3][3];
    #pragma unroll
    for (int i = 0; i < 3; i++)
        #pragma unroll
        for (int j = 0; j < 3; j++)
            u[i][j] = __ldg(&g_util[xi[i] + yi[j]]);

    float acc = 0.f;
    #pragma unroll
    for (int i = 0; i < 3; i++) {
        float a2 = oyv[0] * u[i][0] + oyv[1] * u[i][1] + oyv[2] * u[i][2];
        acc += oxv[i] * a2;
    }
    out[m] = acc;
}

extern "C" void kernel_launch(void* const* d_in, const int* in_sizes, int n_in,
                              void* d_out, int out_size) {
    const float* pos          = (const float*)d_in[0];
    const float* pin_pos      = (const float*)d_in[1];
    const float* node_size_x  = (const float*)d_in[2];
    const float* node_size_y  = (const float*)d_in[3];
    const float* net_weights  = (const float*)d_in[4];
    const int*   netpin_start = (const int*)d_in[5];
    const int*   flat_netpin  = (const int*)d_in[6];
    float* out = (float*)d_out;

    net_kernel<<<(NUM_NETS + 127) / 128, 128>>>(pin_pos, net_weights,
                                                netpin_start, flat_netpin);
    scan_fused_kernel<<<NUM_BINS, NUM_BINS>>>();
    node_kernel<<<(NUM_MOVABLE + 255) / 256, 256>>>(pos, node_size_x,
                                                    node_size_y, out);
}

// round 4
// speedup vs baseline: 3.0152x; 1.0502x over previous
#include <cuda_runtime.h>
#include <math.h>

#define NUM_BINS    128
#define NUM_NETS    100000
#define NUM_NODES   200000
#define NUM_MOVABLE 180000
#define NUM_PINS    400000

#define SB       7.8125f            // bin size (1000/128), exact in fp32
#define INV_SB   0.128f             // approx 1/SB; corrected in bin_of
#define BIN_AREA 61.03515625f       // SB*SB, exact
#define CXU (1.0f / (BIN_AREA * 1.5f))
#define CYU (1.0f / (BIN_AREA * 1.4f))

// Scratch. g_diff zero at load; scan kernel re-zeroes each invocation.
__device__ __align__(16) float2 g_diff[NUM_BINS * NUM_BINS]; // diff array [x*128+y]
__device__ float2 g_pref[NUM_BINS * NUM_BINS];               // after y-prefix
__device__ float  g_util[NUM_BINS * NUM_BINS];               // final util [x*128+y]
__device__ int    g_ctr;                                     // scan grid barrier (reset by node_kernel)

__device__ __forceinline__ int bin_of(float v) {
    int b = (int)(v * INV_SB);
    b = max(0, min(NUM_BINS - 1, b));
    if (v < (float)b * SB) b--;
    else if (v >= (float)(b + 1) * SB) b++;
    return max(0, min(NUM_BINS - 1, b));
}

__device__ __forceinline__ void red_add2(float2* addr, float a, float b) {
    asm volatile("red.global.add.v2.f32 [%0], {%1, %2};"
                 :: "l"(addr), "f"(a), "f"(b) : "memory");
}
__device__ __forceinline__ void red_add4(float2* addr, float a0, float b0,
                                         float a1, float b1) {
    asm volatile("red.global.add.v4.f32 [%0], {%1, %2, %3, %4};"
                 :: "l"(addr), "f"(a0), "f"(b0), "f"(a1), "f"(b1) : "memory");
}

// Emit the <=4 y-deltas of one x-row; merge adjacent pairs into v4 when the
// first index is even (16B-aligned).
__device__ __forceinline__ void emit_row(float2* rowp, float a, float b,
                                         int y0, int y1,
                                         float yv0, float yv1, float yv2, float yv3) {
    if ((y0 & 1) == 0) {            // y0 even => y0+1 <= 127, aligned pair
        red_add4(rowp + y0, a * yv0, b * yv0, a * yv1, b * yv1);
    } else {
        red_add2(rowp + y0, a * yv0, b * yv0);
        if (y0 + 1 < NUM_BINS) red_add2(rowp + y0 + 1, a * yv1, b * yv1);
    }
    if ((y1 & 1) == 0) {
        red_add4(rowp + y1, a * yv2, b * yv2, a * yv3, b * yv3);
    } else {
        red_add2(rowp + y1, a * yv2, b * yv2);
        if (y1 + 1 < NUM_BINS) red_add2(rowp + y1 + 1, a * yv3, b * yv3);
    }
}

// One thread per PIN; each quad of lanes cooperates on one net.
//   - flat_netpin load is fully coalesced
//   - pin gathers: 2 independent scattered loads per lane (64/warp in flight)
//   - bbox via 2 rounds of quad shfl_xor
//   - emission: lane q owns x-row q of the 4-row difference stencil
__global__ void net_kernel(const float* __restrict__ pin_pos,
                           const float* __restrict__ net_weights,
                           const int*   __restrict__ netpin_start,
                           const int*   __restrict__ flat_netpin) {
    int gid = blockIdx.x * blockDim.x + threadIdx.x;
    int n = gid >> 2;              // net id
    int q = gid & 3;               // lane-in-quad
    if (n >= NUM_NETS) return;

    int s = __ldg(netpin_start + n);
    int e = __ldg(netpin_start + n + 1);

    float xmn = 3.4e38f, xmx = -3.4e38f, ymn = 3.4e38f, ymx = -3.4e38f;
    int i = s + q;
    if (i < e) {                   // common case: exactly one iteration per lane
        int p = __ldg(flat_netpin + i);
        float px = __ldg(pin_pos + p);
        float py = __ldg(pin_pos + p + NUM_PINS);
        xmn = px; xmx = px; ymn = py; ymx = py;
        for (i += 4; i < e; i += 4) {      // rarely taken (pin count > 4)
            int p2 = __ldg(flat_netpin + i);
            float px2 = __ldg(pin_pos + p2);
            float py2 = __ldg(pin_pos + p2 + NUM_PINS);
            xmn = fminf(xmn, px2); xmx = fmaxf(xmx, px2);
            ymn = fminf(ymn, py2); ymx = fmaxf(ymx, py2);
        }
    }

    // quad reduce (lanes q^1 then q^2)
    #pragma unroll
    for (int o = 1; o <= 2; o <<= 1) {
        xmn = fminf(xmn, __shfl_xor_sync(0xffffffffu, xmn, o));
        xmx = fmaxf(xmx, __shfl_xor_sync(0xffffffffu, xmx, o));
        ymn = fminf(ymn, __shfl_xor_sync(0xffffffffu, ymn, o));
        ymx = fmaxf(ymx, __shfl_xor_sync(0xffffffffu, ymx, o));
    }

    float w  = __ldg(net_weights + n);
    float dx = xmx - xmn, dy = ymx - ymn;
    float cx = (dy > 0.f) ? (w / dy) : 0.f;   // scales map_x
    float cy = (dx > 0.f) ? (w / dx) : 0.f;   // scales map_y
    if (cx == 0.f && cy == 0.f) return;       // also catches empty nets (inf bbox)

    int x0 = bin_of(xmn), x1 = bin_of(xmx);
    int y0 = bin_of(ymn), y1 = bin_of(ymx);

    float v0x = (float)(x0 + 1) * SB - xmn;
    float v1x = xmx - (float)x1 * SB;
    float v0y = (float)(y0 + 1) * SB - ymn;
    float v1y = ymx - (float)y1 * SB;

    float yv0 = v0y, yv1 = SB - v0y, yv2 = v1y - SB, yv3 = -v1y;

    // Lane q handles x-row q of {x0, x0+1, x1, x1+1} with delta
    // {v0x, SB-v0x, v1x-SB, -v1x}. Overlapping rows (x0==x1 etc.) sum
    // correctly through the atomics.
    int   xp   = ((q & 2) ? x1 : x0) + (q & 1);
    float base = (q & 2) ? (v1x - SB) : v0x;
    float alt  = (q & 2) ? (-v1x)     : (SB - v0x);
    float xv   = (q & 1) ? alt : base;

    if (xp < NUM_BINS)
        emit_row(g_diff + xp * NUM_BINS, xv * cx, xv * cy, y0, y1, yv0, yv1, yv2, yv3);
}

__device__ __forceinline__ float2 block_scan_128(float2 v, float2* wsum) {
    int t = threadIdx.x, lane = t & 31, w = t >> 5;
    #pragma unroll
    for (int o = 1; o < 32; o <<= 1) {
        float ax = __shfl_up_sync(0xffffffffu, v.x, o);
        float ay = __shfl_up_sync(0xffffffffu, v.y, o);
        if (lane >= o) { v.x += ax; v.y += ay; }
    }
    if (lane == 31) wsum[w] = v;
    __syncthreads();
    float ox = 0.f, oy = 0.f;
    #pragma unroll
    for (int k = 0; k < 3; k++)
        if (w > k) { ox += wsum[k].x; oy += wsum[k].y; }
    v.x += ox; v.y += oy;
    return v;
}

// 128 blocks (all wave-1 resident): block b scans row b (y-prefix, re-zeroing
// g_diff), grid-barriers via monotone counter, then scans column b (x-prefix)
// and emits util. g_ctr reset by node_kernel afterwards.
__global__ void scan_fused_kernel() {
    __shared__ float2 wsum[4];
    int b = blockIdx.x, t = threadIdx.x;

    float2 v = g_diff[b * NUM_BINS + t];
    v = block_scan_128(v, wsum);
    g_pref[b * NUM_BINS + t] = v;
    g_diff[b * NUM_BINS + t] = make_float2(0.f, 0.f);

    __threadfence();
    __syncthreads();
    if (t == 0) {
        atomicAdd(&g_ctr, 1);
        while (atomicAdd(&g_ctr, 0) < NUM_BINS) __nanosleep(40);
    }
    __syncthreads();
    __threadfence();

    float2 c;
    {
        const float2* p = g_pref + t * NUM_BINS + b;
        asm volatile("ld.global.cg.v2.f32 {%0, %1}, [%2];"
                     : "=f"(c.x), "=f"(c.y) : "l"(p));
    }
    __syncthreads();   // reuse wsum safely
    c = block_scan_128(c, wsum);
    float u = fmaxf(c.x * CXU, c.y * CYU);
    u = fminf(fmaxf(u, 0.5f), 2.0f);
    g_util[t * NUM_BINS + b] = u;
}

// Per movable node: branch-free 3x3 (span <= 3 bins/axis since size < 8 < 2*SB).
__global__ void node_kernel(const float* __restrict__ pos,
                            const float* __restrict__ nszx,
                            const float* __restrict__ nszy,
                            float* __restrict__ out) {
    int m = blockIdx.x * blockDim.x + threadIdx.x;
    if (m >= NUM_MOVABLE) return;
    if (m == 0) g_ctr = 0;                    // reset scan barrier for next replay
    float nx = __ldg(pos + m), ny = __ldg(pos + m + NUM_NODES);
    float sx = __ldg(nszx + m), sy = __ldg(nszy + m);
    float xh = nx + sx, yh = ny + sy;

    int x0 = bin_of(nx);
    int y0 = bin_of(ny);

    float oxv[3], oyv[3];
    int   xi[3], yi[3];
    #pragma unroll
    for (int k = 0; k < 3; k++) {
        float bx = (float)(x0 + k) * SB;
        oxv[k] = fmaxf(fminf(bx + SB, xh) - fmaxf(bx, nx), 0.f);
        xi[k]  = min(x0 + k, NUM_BINS - 1) * NUM_BINS;
        float by = (float)(y0 + k) * SB;
        oyv[k] = fmaxf(fminf(by + SB, yh) - fmaxf(by, ny), 0.f);
        yi[k]  = min(y0 + k, NUM_BINS - 1);
    }

    float u[3][3];
    #pragma unroll
    for (int i = 0; i < 3; i++)
        #pragma unroll
        for (int j = 0; j < 3; j++)
            u[i][j] = __ldg(&g_util[xi[i] + yi[j]]);

    float acc = 0.f;
    #pragma unroll
    for (int i = 0; i < 3; i++) {
        float a2 = oyv[0] * u[i][0] + oyv[1] * u[i][1] + oyv[2] * u[i][2];
        acc += oxv[i] * a2;
    }
    out[m] = acc;
}

extern "C" void kernel_launch(void* const* d_in, const int* in_sizes, int n_in,
                              void* d_out, int out_size) {
    const float* pos          = (const float*)d_in[0];
    const float* pin_pos      = (const float*)d_in[1];
    const float* node_size_x  = (const float*)d_in[2];
    const float* node_size_y  = (const float*)d_in[3];
    const float* net_weights  = (const float*)d_in[4];
    const int*   netpin_start = (const int*)d_in[5];
    const int*   flat_netpin  = (const int*)d_in[6];
    float* out = (float*)d_out;

    net_kernel<<<(NUM_NETS * 4 + 255) / 256, 256>>>(pin_pos, net_weights,
                                                    netpin_start, flat_netpin);
    scan_fused_kernel<<<NUM_BINS, NUM_BINS>>>();
    node_kernel<<<(NUM_MOVABLE + 255) / 256, 256>>>(pos, node_size_x,
                                                    node_size_y, out);
}

// round 5
// speedup vs baseline: 3.5453x; 1.1758x over previous
#include <cuda_runtime.h>
#include <math.h>

#define NUM_BINS    128
#define NUM_NETS    100000
#define NUM_NODES   200000
#define NUM_MOVABLE 180000
#define NUM_PINS    400000
#define NREP        8               // replicas of the atomic diff array

#define SB       7.8125f            // bin size (1000/128), exact in fp32
#define INV_SB   0.128f             // approx 1/SB; corrected in bin_of
#define BIN_AREA 61.03515625f       // SB*SB, exact
#define CXU (1.0f / (BIN_AREA * 1.5f))
#define CYU (1.0f / (BIN_AREA * 1.4f))

// Scratch. g_diff zero at load; scan kernel re-zeroes each invocation.
// NREP replicas spread the atomic traffic over 8x more L2 lines/slices.
__device__ __align__(16) float2 g_diff[NREP][NUM_BINS * NUM_BINS];
__device__ float2 g_pref[NUM_BINS * NUM_BINS];               // after y-prefix
__device__ float  g_util[NUM_BINS * NUM_BINS];               // final util [x*128+y]
__device__ int    g_ctr;                                     // scan grid barrier (reset by node_kernel)

__device__ __forceinline__ int bin_of(float v) {
    int b = (int)(v * INV_SB);
    b = max(0, min(NUM_BINS - 1, b));
    if (v < (float)b * SB) b--;
    else if (v >= (float)(b + 1) * SB) b++;
    return max(0, min(NUM_BINS - 1, b));
}

__device__ __forceinline__ void red_add2(float2* addr, float a, float b) {
    asm volatile("red.global.add.v2.f32 [%0], {%1, %2};"
                 :: "l"(addr), "f"(a), "f"(b) : "memory");
}
__device__ __forceinline__ void red_add4(float2* addr, float a0, float b0,
                                         float a1, float b1) {
    asm volatile("red.global.add.v4.f32 [%0], {%1, %2, %3, %4};"
                 :: "l"(addr), "f"(a0), "f"(b0), "f"(a1), "f"(b1) : "memory");
}

// Emit the <=4 y-deltas of one x-row; merge adjacent pairs into v4 when the
// first index is even (16B-aligned).
__device__ __forceinline__ void emit_row(float2* rowp, float a, float b,
                                         int y0, int y1,
                                         float yv0, float yv1, float yv2, float yv3) {
    if ((y0 & 1) == 0) {            // y0 even => y0+1 <= 127, aligned pair
        red_add4(rowp + y0, a * yv0, b * yv0, a * yv1, b * yv1);
    } else {
        red_add2(rowp + y0, a * yv0, b * yv0);
        if (y0 + 1 < NUM_BINS) red_add2(rowp + y0 + 1, a * yv1, b * yv1);
    }
    if ((y1 & 1) == 0) {
        red_add4(rowp + y1, a * yv2, b * yv2, a * yv3, b * yv3);
    } else {
        red_add2(rowp + y1, a * yv2, b * yv2);
        if (y1 + 1 < NUM_BINS) red_add2(rowp + y1 + 1, a * yv3, b * yv3);
    }
}

// One thread per PIN; each quad of lanes cooperates on one net.
__global__ void net_kernel(const float* __restrict__ pin_pos,
                           const float* __restrict__ net_weights,
                           const int*   __restrict__ netpin_start,
                           const int*   __restrict__ flat_netpin) {
    int gid = blockIdx.x * blockDim.x + threadIdx.x;
    int n = gid >> 2;              // net id
    int q = gid & 3;               // lane-in-quad
    if (n >= NUM_NETS) return;

    int s = __ldg(netpin_start + n);
    int e = __ldg(netpin_start + n + 1);

    float xmn = 3.4e38f, xmx = -3.4e38f, ymn = 3.4e38f, ymx = -3.4e38f;
    int i = s + q;
    if (i < e) {                   // common case: exactly one iteration per lane
        int p = __ldg(flat_netpin + i);
        float px = __ldg(pin_pos + p);
        float py = __ldg(pin_pos + p + NUM_PINS);
        xmn = px; xmx = px; ymn = py; ymx = py;
        for (i += 4; i < e; i += 4) {      // rarely taken (pin count > 4)
            int p2 = __ldg(flat_netpin + i);
            float px2 = __ldg(pin_pos + p2);
            float py2 = __ldg(pin_pos + p2 + NUM_PINS);
            xmn = fminf(xmn, px2); xmx = fmaxf(xmx, px2);
            ymn = fminf(ymn, py2); ymx = fmaxf(ymx, py2);
        }
    }

    // quad reduce (lanes q^1 then q^2)
    #pragma unroll
    for (int o = 1; o <= 2; o <<= 1) {
        xmn = fminf(xmn, __shfl_xor_sync(0xffffffffu, xmn, o));
        xmx = fmaxf(xmx, __shfl_xor_sync(0xffffffffu, xmx, o));
        ymn = fminf(ymn, __shfl_xor_sync(0xffffffffu, ymn, o));
        ymx = fmaxf(ymx, __shfl_xor_sync(0xffffffffu, ymx, o));
    }

    float w  = __ldg(net_weights + n);
    float dx = xmx - xmn, dy = ymx - ymn;
    float cx = (dy > 0.f) ? (w / dy) : 0.f;   // scales map_x
    float cy = (dx > 0.f) ? (w / dx) : 0.f;   // scales map_y
    if (cx == 0.f && cy == 0.f) return;       // also catches empty nets (inf bbox)

    int x0 = bin_of(xmn), x1 = bin_of(xmx);
    int y0 = bin_of(ymn), y1 = bin_of(ymx);

    float v0x = (float)(x0 + 1) * SB - xmn;
    float v1x = xmx - (float)x1 * SB;
    float v0y = (float)(y0 + 1) * SB - ymn;
    float v1y = ymx - (float)y1 * SB;

    float yv0 = v0y, yv1 = SB - v0y, yv2 = v1y - SB, yv3 = -v1y;

    // Lane q handles x-row q of {x0, x0+1, x1, x1+1} with delta
    // {v0x, SB-v0x, v1x-SB, -v1x}. Overlaps sum correctly via atomics.
    int   xp   = ((q & 2) ? x1 : x0) + (q & 1);
    float base = (q & 2) ? (v1x - SB) : v0x;
    float alt  = (q & 2) ? (-v1x)     : (SB - v0x);
    float xv   = (q & 1) ? alt : base;

    if (xp < NUM_BINS)
        emit_row(g_diff[n & (NREP - 1)] + xp * NUM_BINS, xv * cx, xv * cy,
                 y0, y1, yv0, yv1, yv2, yv3);
}

__device__ __forceinline__ float2 block_scan_128(float2 v, float2* wsum) {
    int t = threadIdx.x, lane = t & 31, w = t >> 5;
    #pragma unroll
    for (int o = 1; o < 32; o <<= 1) {
        float ax = __shfl_up_sync(0xffffffffu, v.x, o);
        float ay = __shfl_up_sync(0xffffffffu, v.y, o);
        if (lane >= o) { v.x += ax; v.y += ay; }
    }
    if (lane == 31) wsum[w] = v;
    __syncthreads();
    float ox = 0.f, oy = 0.f;
    #pragma unroll
    for (int k = 0; k < 3; k++)
        if (w > k) { ox += wsum[k].x; oy += wsum[k].y; }
    v.x += ox; v.y += oy;
    return v;
}

// 128 blocks (all wave-1 resident): block b sums the NREP replicas of row b,
// scans it (y-prefix) and re-zeroes the replicas, grid-barriers, then scans
// column b (x-prefix) and emits util. g_ctr reset by node_kernel afterwards.
__global__ void scan_fused_kernel() {
    __shared__ float2 wsum[4];
    int b = blockIdx.x, t = threadIdx.x;

    float2 v = make_float2(0.f, 0.f);
    #pragma unroll
    for (int r = 0; r < NREP; r++) {
        float2 d = g_diff[r][b * NUM_BINS + t];
        v.x += d.x; v.y += d.y;
        g_diff[r][b * NUM_BINS + t] = make_float2(0.f, 0.f);
    }
    v = block_scan_128(v, wsum);
    g_pref[b * NUM_BINS + t] = v;

    __threadfence();
    __syncthreads();
    if (t == 0) {
        atomicAdd(&g_ctr, 1);
        while (atomicAdd(&g_ctr, 0) < NUM_BINS) __nanosleep(40);
    }
    __syncthreads();
    __threadfence();

    float2 c;
    {
        const float2* p = g_pref + t * NUM_BINS + b;
        asm volatile("ld.global.cg.v2.f32 {%0, %1}, [%2];"
                     : "=f"(c.x), "=f"(c.y) : "l"(p));
    }
    __syncthreads();   // reuse wsum safely
    c = block_scan_128(c, wsum);
    float u = fmaxf(c.x * CXU, c.y * CYU);
    u = fminf(fmaxf(u, 0.5f), 2.0f);
    g_util[t * NUM_BINS + b] = u;
}

// Per movable node: branch-free 3x3 (span <= 3 bins/axis since size < 8 < 2*SB).
__global__ void node_kernel(const float* __restrict__ pos,
                            const float* __restrict__ nszx,
                            const float* __restrict__ nszy,
                            float* __restrict__ out) {
    int m = blockIdx.x * blockDim.x + threadIdx.x;
    if (m >= NUM_MOVABLE) return;
    if (m == 0) g_ctr = 0;                    // reset scan barrier for next replay
    float nx = __ldg(pos + m), ny = __ldg(pos + m + NUM_NODES);
    float sx = __ldg(nszx + m), sy = __ldg(nszy + m);
    float xh = nx + sx, yh = ny + sy;

    int x0 = bin_of(nx);
    int y0 = bin_of(ny);

    float oxv[3], oyv[3];
    int   xi[3], yi[3];
    #pragma unroll
    for (int k = 0; k < 3; k++) {
        float bx = (float)(x0 + k) * SB;
        oxv[k] = fmaxf(fminf(bx + SB, xh) - fmaxf(bx, nx), 0.f);
        xi[k]  = min(x0 + k, NUM_BINS - 1) * NUM_BINS;
        float by = (float)(y0 + k) * SB;
        oyv[k] = fmaxf(fminf(by + SB, yh) - fmaxf(by, ny), 0.f);
        yi[k]  = min(y0 + k, NUM_BINS - 1);
    }

    float u[3][3];
    #pragma unroll
    for (int i = 0; i < 3; i++)
        #pragma unroll
        for (int j = 0; j < 3; j++)
            u[i][j] = __ldg(&g_util[xi[i] + yi[j]]);

    float acc = 0.f;
    #pragma unroll
    for (int i = 0; i < 3; i++) {
        float a2 = oyv[0] * u[i][0] + oyv[1] * u[i][1] + oyv[2] * u[i][2];
        acc += oxv[i] * a2;
    }
    out[m] = acc;
}

extern "C" void kernel_launch(void* const* d_in, const int* in_sizes, int n_in,
                              void* d_out, int out_size) {
    const float* pos          = (const float*)d_in[0];
    const float* pin_pos      = (const float*)d_in[1];
    const float* node_size_x  = (const float*)d_in[2];
    const float* node_size_y  = (const float*)d_in[3];
    const float* net_weights  = (const float*)d_in[4];
    const int*   netpin_start = (const int*)d_in[5];
    const int*   flat_netpin  = (const int*)d_in[6];
    float* out = (float*)d_out;

    net_kernel<<<(NUM_NETS * 4 + 255) / 256, 256>>>(pin_pos, net_weights,
                                                    netpin_start, flat_netpin);
    scan_fused_kernel<<<NUM_BINS, NUM_BINS>>>();
    node_kernel<<<(NUM_MOVABLE + 255) / 256, 256>>>(pos, node_size_x,
                                                    node_size_y, out);
}